// round 1
// baseline (speedup 1.0000x reference)
#include <cuda_runtime.h>
#include <math.h>

#define BB 32
#define LL 1024
#define MN 512
#define SD 256
#define VD 64
#define D3 192
#define DM 256
#define NH 8
#define DK 32

// ---------------- scratch (device globals; no allocation allowed) ----------------
__device__ float g_pos_sum[MN * D3];
__device__ float g_gamma[BB * MN * DM];
__device__ float g_xm[BB * MN * D3];
__device__ float g_pe[BB * MN * D3];
__device__ float g_Q[BB * LL * DM];
__device__ float g_K[BB * MN * DM];
__device__ float g_V[BB * MN * DM];
__device__ float g_attn[BB * LL * DM];
__device__ float g_fc[BB * LL * DM];

// ---------------- pos_sum[j,d] = sum_i emb[clip(j-i,-30,30)+30, d] ----------------
__global__ void possum_kernel(const float* __restrict__ emb) {
    int j = blockIdx.x;
    int d = threadIdx.x;   // 192 threads
    float acc = 0.f;
    #pragma unroll
    for (int delta = -29; delta <= 29; delta++) {
        int i = j - delta;
        if (i >= 0 && i < MN) acc += emb[(delta + 30) * D3 + d];
    }
    int cpos = j - 29;        // count for delta = +30
    if (cpos > 0) acc += (float)cpos * emb[60 * D3 + d];
    int cneg = 482 - j;       // count for delta = -30
    if (cneg > 0) acc += (float)cneg * emb[0 * D3 + d];
    g_pos_sum[j * D3 + d] = acc;
}

// ---------------- generic GEMM: C[M,N] = A[M,K] * W[N,K]^T (+bias, opt sigmoid) ----
__global__ void gemm_kernel(const float* __restrict__ A, const float* __restrict__ W,
                            const float* __restrict__ bias, float* __restrict__ C,
                            int M, int N, int Kd, int sigmoidFlag) {
    __shared__ float As[16][68];
    __shared__ float Ws[16][68];
    int tid = threadIdx.x;
    int tx = tid & 15, ty = tid >> 4;
    int m0 = blockIdx.y * 64, n0 = blockIdx.x * 64;

    float acc[4][4];
    #pragma unroll
    for (int i = 0; i < 4; i++)
        #pragma unroll
        for (int j = 0; j < 4; j++) acc[i][j] = 0.f;

    for (int kk = 0; kk < Kd; kk += 16) {
        #pragma unroll
        for (int l = 0; l < 4; l++) {
            int idx = tid + l * 256;
            int m = idx >> 4, k = idx & 15;
            As[k][m] = A[(size_t)(m0 + m) * Kd + kk + k];
            Ws[k][m] = W[(size_t)(n0 + m) * Kd + kk + k];
        }
        __syncthreads();
        #pragma unroll
        for (int k = 0; k < 16; k++) {
            float4 av = *(const float4*)&As[k][ty * 4];
            float4 bv = *(const float4*)&Ws[k][tx * 4];
            float a[4] = {av.x, av.y, av.z, av.w};
            float b[4] = {bv.x, bv.y, bv.z, bv.w};
            #pragma unroll
            for (int i = 0; i < 4; i++)
                #pragma unroll
                for (int j = 0; j < 4; j++) acc[i][j] += a[i] * b[j];
        }
        __syncthreads();
    }

    #pragma unroll
    for (int i = 0; i < 4; i++) {
        int r = m0 + ty * 4 + i;
        float o[4];
        #pragma unroll
        for (int j = 0; j < 4; j++) {
            float v = acc[i][j];
            if (bias) v += bias[n0 + tx * 4 + j];
            if (sigmoidFlag) v = 1.f / (1.f + __expf(-v));
            o[j] = v;
        }
        *(float4*)&C[(size_t)r * N + n0 + tx * 4] = make_float4(o[0], o[1], o[2], o[3]);
    }
}

// ---------------- multi-scale conv: xm[b,s,0:64|64:128|128:192] = conv3|5|7 --------
template <int K>
__device__ __forceinline__ void conv_do(float* xs, float* ws,
                                        const float* __restrict__ w,
                                        const float* __restrict__ bias,
                                        int coff, int b, int s0, int tid) {
    __syncthreads();   // previous users of ws done
    // stage weights transposed: ws[(i*K + t)*64 + oc] = w[oc][i][t]
    for (int idx = tid; idx < 64 * 64 * K; idx += 256) {
        int t = idx % K;
        int i = (idx / K) & 63;
        int o = idx / (K * 64);
        ws[(i * K + t) * 64 + o] = w[idx];
    }
    __syncthreads();

    int oc = tid & 63;
    int pbase = (tid >> 6) * 16;
    float acc[16];
    float bv = bias[oc];
    #pragma unroll
    for (int pp = 0; pp < 16; pp++) acc[pp] = bv;

    for (int i = 0; i < 64; i++) {
        float xvr[16 + K - 1];
        #pragma unroll
        for (int j = 0; j < 16 + K - 1; j++)
            xvr[j] = xs[(pbase + j + 3 - K / 2) * 64 + i];
        #pragma unroll
        for (int t = 0; t < K; t++) {
            float wv = ws[(i * K + t) * 64 + oc];
            #pragma unroll
            for (int pp = 0; pp < 16; pp++) acc[pp] += xvr[pp + t] * wv;
        }
    }
    #pragma unroll
    for (int pp = 0; pp < 16; pp++)
        g_xm[((size_t)b * MN + s0 + pbase + pp) * D3 + coff + oc] = acc[pp];
}

__global__ void conv_kernel(const float* __restrict__ xv,
                            const float* __restrict__ w3, const float* __restrict__ b3,
                            const float* __restrict__ w5, const float* __restrict__ b5,
                            const float* __restrict__ w7, const float* __restrict__ b7) {
    extern __shared__ float sh[];
    float* xs = sh;             // [70][64] halo tile
    float* ws = sh + 70 * 64;   // weight stage (max 64*64*7)
    int blk = blockIdx.x;
    int b = blk >> 3;
    int s0 = (blk & 7) * 64;
    int tid = threadIdx.x;

    for (int idx = tid; idx < 70 * 64; idx += 256) {
        int r = idx >> 6, i = idx & 63;
        int s = s0 - 3 + r;
        xs[idx] = (s >= 0 && s < MN) ? xv[((size_t)b * MN + s) * VD + i] : 0.f;
    }
    conv_do<3>(xs, ws, w3, b3, 0, b, s0, tid);
    conv_do<5>(xs, ws, w5, b5, 64, b, s0, tid);
    conv_do<7>(xs, ws, w7, b7, 128, b, s0, tid);
}

// ---------------- rel-pos encoding (closed form, elementwise) ----------------------
__global__ void pe_kernel(const float* __restrict__ emb,
                          const float* __restrict__ dww, const float* __restrict__ dwb) {
    int idx = blockIdx.x * 256 + threadIdx.x;
    if (idx >= BB * MN * D3) return;
    int d = idx % D3;
    int j = (idx / D3) & (MN - 1);
    float xc = g_xm[idx];
    float fC = xc + emb[30 * D3 + d];
    float fL = 0.f, fR = 0.f;
    if (j > 0)      fL = g_xm[idx - D3] + emb[29 * D3 + d];
    if (j < MN - 1) fR = g_xm[idx + D3] + emb[31 * D3 + d];
    float diag = fL * dww[d * 3 + 0] + fC * dww[d * 3 + 1] + fR * dww[d * 3 + 2] + dwb[d];
    g_pe[idx] = xc + (g_pos_sum[j * D3 + d] - fC + diag) * (1.0f / (float)MN);
}

// ---------------- attention: per (b,h), K/V resident in smem -----------------------
__global__ void attn_kernel() {
    extern __shared__ float sh[];
    float* Ks = sh;             // [512][32]
    float* Vs = sh + MN * DK;   // [512][32]
    int blk = blockIdx.x;       // b*32 + h*4 + qt
    int qt = blk & 3;
    int h = (blk >> 2) & 7;
    int b = blk >> 5;
    int tid = threadIdx.x;

    const float* Kg = g_K + (size_t)b * MN * DM + h * DK;
    const float* Vg = g_V + (size_t)b * MN * DM + h * DK;
    for (int idx = tid; idx < MN * 8; idx += 256) {
        int s = idx >> 3, d4 = idx & 7;
        *(float4*)&Ks[s * DK + d4 * 4] = *(const float4*)&Kg[(size_t)s * DM + d4 * 4];
        *(float4*)&Vs[s * DK + d4 * 4] = *(const float4*)&Vg[(size_t)s * DM + d4 * 4];
    }
    __syncthreads();

    int l = qt * 256 + tid;
    const float* Qg = g_Q + ((size_t)b * LL + l) * DM + h * DK;
    float q[DK];
    #pragma unroll
    for (int d4 = 0; d4 < 8; d4++) {
        float4 v = *(const float4*)&Qg[d4 * 4];
        q[d4 * 4 + 0] = v.x * 0.17677669529663687f;   // 1/sqrt(32)
        q[d4 * 4 + 1] = v.y * 0.17677669529663687f;
        q[d4 * 4 + 2] = v.z * 0.17677669529663687f;
        q[d4 * 4 + 3] = v.w * 0.17677669529663687f;
    }
    float lsum = 0.f;
    float o[DK];
    #pragma unroll
    for (int d = 0; d < DK; d++) o[d] = 0.f;

    // scores are bounded well inside expf's range: no max-tracking needed
    for (int s = 0; s < MN; s++) {
        float x = 0.f;
        const float4* K4 = (const float4*)(Ks + s * DK);
        #pragma unroll
        for (int d4 = 0; d4 < 8; d4++) {
            float4 kv = K4[d4];
            x += q[d4 * 4 + 0] * kv.x + q[d4 * 4 + 1] * kv.y
               + q[d4 * 4 + 2] * kv.z + q[d4 * 4 + 3] * kv.w;
        }
        float p = __expf(x);
        lsum += p;
        const float4* V4 = (const float4*)(Vs + s * DK);
        #pragma unroll
        for (int d4 = 0; d4 < 8; d4++) {
            float4 vv = V4[d4];
            o[d4 * 4 + 0] += p * vv.x;
            o[d4 * 4 + 1] += p * vv.y;
            o[d4 * 4 + 2] += p * vv.z;
            o[d4 * 4 + 3] += p * vv.w;
        }
    }
    float inv = 1.f / lsum;
    float* Og = g_attn + ((size_t)b * LL + l) * DM + h * DK;
    #pragma unroll
    for (int d4 = 0; d4 < 8; d4++) {
        *(float4*)&Og[d4 * 4] = make_float4(o[d4 * 4] * inv, o[d4 * 4 + 1] * inv,
                                            o[d4 * 4 + 2] * inv, o[d4 * 4 + 3] * inv);
    }
}

// ---------------- gate * fc + residual + LayerNorm ---------------------------------
__global__ void final_kernel(const float* __restrict__ xs,
                             const float* __restrict__ lnw, const float* __restrict__ lnb,
                             float* __restrict__ out) {
    __shared__ float red[16];
    int row = blockIdx.x;          // b*1024 + l
    int b = row >> 10;
    int l = row & 1023;
    int c = threadIdx.x;
    size_t off = (size_t)row * DM + c;
    float fcv = g_fc[off];
    float gam = g_gamma[((size_t)b * MN + (l & (MN - 1))) * DM + c];
    float v = xs[off] + gam * fcv;

    float s1 = v, s2 = v * v;
    #pragma unroll
    for (int d = 16; d; d >>= 1) {
        s1 += __shfl_xor_sync(0xFFFFFFFFu, s1, d);
        s2 += __shfl_xor_sync(0xFFFFFFFFu, s2, d);
    }
    int warp = c >> 5, lane = c & 31;
    if (lane == 0) { red[warp] = s1; red[8 + warp] = s2; }
    __syncthreads();
    float t1 = 0.f, t2 = 0.f;
    #pragma unroll
    for (int w = 0; w < 8; w++) { t1 += red[w]; t2 += red[8 + w]; }
    float mu = t1 * (1.f / 256.f);
    float var = t2 * (1.f / 256.f) - mu * mu;
    out[off] = (v - mu) * rsqrtf(var + 1e-5f) * lnw[c] + lnb[c];
}

// ---------------- launch -----------------------------------------------------------
extern "C" void kernel_launch(void* const* d_in, const int* in_sizes, int n_in,
                              void* d_out, int out_size) {
    const float* x_spatial  = (const float*)d_in[0];
    const float* x_velocity = (const float*)d_in[1];
    const float* Wg    = (const float*)d_in[2];
    const float* ms_w3 = (const float*)d_in[3];
    const float* ms_b3 = (const float*)d_in[4];
    const float* ms_w5 = (const float*)d_in[5];
    const float* ms_b5 = (const float*)d_in[6];
    const float* ms_w7 = (const float*)d_in[7];
    const float* ms_b7 = (const float*)d_in[8];
    const float* rel_emb = (const float*)d_in[9];
    const float* dw_w  = (const float*)d_in[10];
    const float* dw_b  = (const float*)d_in[11];
    const float* Wq    = (const float*)d_in[12];
    const float* Wk    = (const float*)d_in[13];
    const float* Wv    = (const float*)d_in[14];
    const float* fc_w  = (const float*)d_in[15];
    const float* fc_b  = (const float*)d_in[16];
    const float* ln_w  = (const float*)d_in[17];
    const float* ln_b  = (const float*)d_in[18];
    float* out = (float*)d_out;

    float *p_gamma, *p_pe, *p_Q, *p_K, *p_V, *p_attn, *p_fc;
    cudaGetSymbolAddress((void**)&p_gamma, g_gamma);
    cudaGetSymbolAddress((void**)&p_pe,    g_pe);
    cudaGetSymbolAddress((void**)&p_Q,     g_Q);
    cudaGetSymbolAddress((void**)&p_K,     g_K);
    cudaGetSymbolAddress((void**)&p_V,     g_V);
    cudaGetSymbolAddress((void**)&p_attn,  g_attn);
    cudaGetSymbolAddress((void**)&p_fc,    g_fc);

    const int CONV_SMEM = (70 * 64 + 64 * 64 * 7) * 4;   // 132,608 B
    const int ATTN_SMEM = 2 * MN * DK * 4;               // 131,072 B
    cudaFuncSetAttribute(conv_kernel, cudaFuncAttributeMaxDynamicSharedMemorySize, CONV_SMEM);
    cudaFuncSetAttribute(attn_kernel, cudaFuncAttributeMaxDynamicSharedMemorySize, ATTN_SMEM);

    possum_kernel<<<MN, D3>>>(rel_emb);

    // Gamma = sigmoid(x_velocity @ Wg^T)   [16384, 256]
    gemm_kernel<<<dim3(DM / 64, BB * MN / 64), 256>>>(x_velocity, Wg, nullptr, p_gamma,
                                                      BB * MN, DM, VD, 1);
    conv_kernel<<<BB * (MN / 64), 256, CONV_SMEM>>>(x_velocity, ms_w3, ms_b3,
                                                    ms_w5, ms_b5, ms_w7, ms_b7);
    pe_kernel<<<(BB * MN * D3 + 255) / 256, 256>>>(rel_emb, dw_w, dw_b);

    // Q / K / V projections
    gemm_kernel<<<dim3(DM / 64, BB * LL / 64), 256>>>(x_spatial, Wq, nullptr, p_Q,
                                                      BB * LL, DM, SD, 0);
    gemm_kernel<<<dim3(DM / 64, BB * MN / 64), 256>>>(p_pe, Wk, nullptr, p_K,
                                                      BB * MN, DM, D3, 0);
    gemm_kernel<<<dim3(DM / 64, BB * MN / 64), 256>>>(p_pe, Wv, nullptr, p_V,
                                                      BB * MN, DM, D3, 0);

    attn_kernel<<<BB * NH * (LL / 256), 256, ATTN_SMEM>>>();

    gemm_kernel<<<dim3(DM / 64, BB * LL / 64), 256>>>(p_attn, fc_w, fc_b, p_fc,
                                                      BB * LL, DM, DM, 0);
    final_kernel<<<BB * LL, 256>>>(x_spatial, ln_w, ln_b, out);
}